// round 3
// baseline (speedup 1.0000x reference)
#include <cuda_runtime.h>

// RK4 step of 2D Burgers-type PDE, (8,2,1024,1024) fp32, periodic wrap,
// 4th-order cross stencils (radius 2).
//
// Stage s computes k_s = f(stage_field), accumulates the RK weighted sum into
// d_out (acc), and writes the next stage field u0 + c*k_s into ping-pong
// __device__ scratch. Stage 4 writes the final result into d_out.

#define IMW 1024
#define IMH 1024
#define HW  (IMW * IMH)
#define NB  8

static __device__ float g_sA[NB * 2 * HW];  // 64 MB
static __device__ float g_sB[NB * 2 * HW];  // 64 MB

__device__ __forceinline__ float4 ld4(const float* __restrict__ p) {
    return *reinterpret_cast<const float4*>(p);
}
__device__ __forceinline__ void st4(float* __restrict__ p, float a, float b, float c, float d) {
    *reinterpret_cast<float4*>(p) = make_float4(a, b, c, d);
}
__device__ __forceinline__ void put4(float* d, float4 v) {
    d[0] = v.x; d[1] = v.y; d[2] = v.z; d[3] = v.w;
}

// STAGE: 1..4
template <int STAGE>
__global__ __launch_bounds__(256) void rk_stage_kernel(
    const float* __restrict__ h,   // original state (8,2,1024,1024)
    float* __restrict__ acc,       // RK accumulator == d_out
    const float* __restrict__ pRe,
    const float* __restrict__ pUA,
    const float* __restrict__ pUB,
    const float* __restrict__ pVA,
    const float* __restrict__ pVB)
{
    const int gid = blockIdx.x * 256 + threadIdx.x;
    const int xq  = gid & 255;          // which group of 4 x's
    const int y   = (gid >> 8) & 1023;
    const int b   = gid >> 18;
    const int x0  = xq << 2;

    const float* sin;
    float*       sout;
    if      (STAGE == 1) { sin = h;    sout = g_sA; }
    else if (STAGE == 2) { sin = g_sA; sout = g_sB; }
    else if (STAGE == 3) { sin = g_sB; sout = g_sA; }
    else                 { sin = g_sA; sout = nullptr; }

    const float nu = 0.001f / pRe[0];
    const float UA = pUA[0], UB = pUB[0], VA = pVA[0], VB = pVB[0];

    const float DX = 0.01f;
    const float inv_dx2 = 1.0f / (DX * DX);
    const float inv_dx  = 1.0f / DX;
    const float c0 = -5.0f, c1 = 4.0f / 3.0f, c2 = -1.0f / 12.0f;  // laplacian taps
    const float d1 = 8.0f / 12.0f, d2 = 1.0f / 12.0f;              // derivative taps

    const int base = b * 2 * HW;
    const float* su = sin + base;
    const float* sv = su + HW;

    const int ym2 = ((y - 2) & 1023) * IMW;
    const int ym1 = ((y - 1) & 1023) * IMW;
    const int yc  = y * IMW;
    const int yp1 = ((y + 1) & 1023) * IMW;
    const int yp2 = ((y + 2) & 1023) * IMW;
    const int xm  = (x0 - 4) & 1023;   // stays 16B-aligned
    const int xp  = (x0 + 4) & 1023;

    // ---- gather u channel (9-point cross, 4-wide) ----
    float u_n2[4], u_n1[4], u_p1[4], u_p2[4], wu[12];
    put4(u_n2, ld4(su + ym2 + x0));
    put4(u_n1, ld4(su + ym1 + x0));
    put4(u_p1, ld4(su + yp1 + x0));
    put4(u_p2, ld4(su + yp2 + x0));
    put4(wu + 0, ld4(su + yc + xm));
    put4(wu + 4, ld4(su + yc + x0));
    put4(wu + 8, ld4(su + yc + xp));

    // ---- gather v channel ----
    float v_n2[4], v_n1[4], v_p1[4], v_p2[4], wv[12];
    put4(v_n2, ld4(sv + ym2 + x0));
    put4(v_n1, ld4(sv + ym1 + x0));
    put4(v_p1, ld4(sv + yp1 + x0));
    put4(v_p2, ld4(sv + yp2 + x0));
    put4(wv + 0, ld4(sv + yc + xm));
    put4(wv + 4, ld4(sv + yc + x0));
    put4(wv + 8, ld4(sv + yc + xp));

    float fu[4], fv[4];
#pragma unroll
    for (int j = 0; j < 4; j++) {
        const float uc = wu[4 + j];
        const float vc = wv[4 + j];

        const float lap_u = (c0 * uc
                           + c1 * (u_n1[j] + u_p1[j] + wu[3 + j] + wu[5 + j])
                           + c2 * (u_n2[j] + u_p2[j] + wu[2 + j] + wu[6 + j])) * inv_dx2;
        const float lap_v = (c0 * vc
                           + c1 * (v_n1[j] + v_p1[j] + wv[3 + j] + wv[5 + j])
                           + c2 * (v_n2[j] + v_p2[j] + wv[2 + j] + wv[6 + j])) * inv_dx2;

        // "u_x" in the reference differentiates along the H axis (rows):
        const float u_x = (d2 * (u_n2[j] - u_p2[j]) + d1 * (u_p1[j] - u_n1[j])) * inv_dx;
        const float v_x = (d2 * (v_n2[j] - v_p2[j]) + d1 * (v_p1[j] - v_n1[j])) * inv_dx;
        // "u_y" differentiates along the W axis (columns):
        const float u_y = (d2 * (wu[2 + j] - wu[6 + j]) + d1 * (wu[5 + j] - wu[3 + j])) * inv_dx;
        const float v_y = (d2 * (wv[2 + j] - wv[6 + j]) + d1 * (wv[5 + j] - wv[3 + j])) * inv_dx;

        fu[j] = nu * lap_u + UA * uc * u_x + UB * vc * u_y;
        fv[j] = nu * lap_v + VA * uc * v_x + VB * vc * v_y;
    }

    const int ou = base + yc + x0;       // offset of u-channel vec
    const int ov = ou + HW;              // offset of v-channel vec

    // original state (center only)
    float hu[4], hv[4];
    if (STAGE == 1) {
#pragma unroll
        for (int j = 0; j < 4; j++) { hu[j] = wu[4 + j]; hv[j] = wv[4 + j]; }
    } else {
        put4(hu, ld4(h + ou));
        put4(hv, ld4(h + ov));
    }

    if (STAGE == 1) {
        // acc = k1 ; stage field = h + (DT/2) k1
        st4(acc + ou, fu[0], fu[1], fu[2], fu[3]);
        st4(acc + ov, fv[0], fv[1], fv[2], fv[3]);
        st4(sout + ou, hu[0] + 0.25f * fu[0], hu[1] + 0.25f * fu[1],
                       hu[2] + 0.25f * fu[2], hu[3] + 0.25f * fu[3]);
        st4(sout + ov, hv[0] + 0.25f * fv[0], hv[1] + 0.25f * fv[1],
                       hv[2] + 0.25f * fv[2], hv[3] + 0.25f * fv[3]);
    } else if (STAGE == 2 || STAGE == 3) {
        float au[4], av[4];
        put4(au, ld4(acc + ou));
        put4(av, ld4(acc + ov));
        // acc += 2 k_s
        st4(acc + ou, au[0] + 2.0f * fu[0], au[1] + 2.0f * fu[1],
                      au[2] + 2.0f * fu[2], au[3] + 2.0f * fu[3]);
        st4(acc + ov, av[0] + 2.0f * fv[0], av[1] + 2.0f * fv[1],
                      av[2] + 2.0f * fv[2], av[3] + 2.0f * fv[3]);
        const float cst = (STAGE == 2) ? 0.25f : 0.5f;  // DT/2 or DT
        st4(sout + ou, hu[0] + cst * fu[0], hu[1] + cst * fu[1],
                       hu[2] + cst * fu[2], hu[3] + cst * fu[3]);
        st4(sout + ov, hv[0] + cst * fv[0], hv[1] + cst * fv[1],
                       hv[2] + cst * fv[2], hv[3] + cst * fv[3]);
    } else {  // STAGE 4: out = h + (DT/6) * (acc + k4)
        float au[4], av[4];
        put4(au, ld4(acc + ou));
        put4(av, ld4(acc + ov));
        const float w = 0.5f / 6.0f;
        st4(acc + ou, hu[0] + w * (au[0] + fu[0]), hu[1] + w * (au[1] + fu[1]),
                      hu[2] + w * (au[2] + fu[2]), hu[3] + w * (au[3] + fu[3]));
        st4(acc + ov, hv[0] + w * (av[0] + fv[0]), hv[1] + w * (av[1] + fv[1]),
                      hv[2] + w * (av[2] + fv[2]), hv[3] + w * (av[3] + fv[3]));
    }
}

extern "C" void kernel_launch(void* const* d_in, const int* in_sizes, int n_in,
                              void* d_out, int out_size)
{
    // Identify inputs robustly: the single large tensor is h; the scalars
    // follow in declaration order Re, UA, UB, VA, VB.
    const float* h = nullptr;
    const float* sc[5] = {nullptr, nullptr, nullptr, nullptr, nullptr};
    int nsc = 0;
    for (int i = 0; i < n_in; i++) {
        if (in_sizes[i] == NB * 2 * HW) {
            h = (const float*)d_in[i];
        } else if (nsc < 5) {
            sc[nsc++] = (const float*)d_in[i];
        }
    }
    const float* Re = sc[0];
    const float* UA = sc[1];
    const float* UB = sc[2];
    const float* VA = sc[3];
    const float* VB = sc[4];

    float* acc = (float*)d_out;

    const int threads = 256;
    const int blocks  = (NB * 2 * HW / 4) / threads / 2;  // = NB*1024 = 8192
    // (each thread covers 4 x-values of one channel-pair site => NB*1024*256 threads)

    rk_stage_kernel<1><<<NB * 1024, threads>>>(h, acc, Re, UA, UB, VA, VB);
    rk_stage_kernel<2><<<NB * 1024, threads>>>(h, acc, Re, UA, UB, VA, VB);
    rk_stage_kernel<3><<<NB * 1024, threads>>>(h, acc, Re, UA, UB, VA, VB);
    rk_stage_kernel<4><<<NB * 1024, threads>>>(h, acc, Re, UA, UB, VA, VB);
    (void)blocks; (void)out_size;
}